// round 15
// baseline (speedup 1.0000x reference)
#include <cuda_runtime.h>
#include <cuda_fp16.h>
#include <math.h>
#include <stdint.h>

#define B_   4
#define T_   2048
#define C_   2048
#define NH   16
#define NKV  4
#define HD   128
#define KVD  (NKV*HD)   // 512
#define M_   (B_*T_)    // 8192

// ---------------- scratch (__device__ globals; no allocs allowed) ----------
__device__ __half s_qh[(size_t)M_ * C_];
__device__ __half s_kh[(size_t)M_ * KVD];
__device__ __half s_vh[(size_t)M_ * KVD];

__device__ __half s_xh[(size_t)M_ * C_];
__device__ __half s_yh[(size_t)M_ * C_];
__device__ __half s_wqh[(size_t)C_ * C_];
__device__ __half s_wkh[(size_t)KVD * C_];
__device__ __half s_wvh[(size_t)KVD * C_];
__device__ __half s_woh[(size_t)C_ * C_];

// ---------------- helpers ---------------------------------------------------
__device__ __forceinline__ uint32_t smem_u32(const void* p) {
    uint32_t a;
    asm("{ .reg .u64 t; cvta.to.shared.u64 t, %1; cvt.u32.u64 %0, t; }"
        : "=r"(a) : "l"(p));
    return a;
}
__device__ __forceinline__ void ldsm4(uint32_t* r, uint32_t addr) {
    asm volatile("ldmatrix.sync.aligned.m8n8.x4.shared.b16 {%0,%1,%2,%3}, [%4];"
                 : "=r"(r[0]), "=r"(r[1]), "=r"(r[2]), "=r"(r[3]) : "r"(addr));
}
__device__ __forceinline__ void ldsm4t(uint32_t* r, uint32_t addr) {
    asm volatile("ldmatrix.sync.aligned.m8n8.x4.trans.shared.b16 {%0,%1,%2,%3}, [%4];"
                 : "=r"(r[0]), "=r"(r[1]), "=r"(r[2]), "=r"(r[3]) : "r"(addr));
}
__device__ __forceinline__ void mma16816h(float* c, const uint32_t* a,
                                          const uint32_t* b) {
    asm volatile(
        "mma.sync.aligned.m16n8k16.row.col.f32.f16.f16.f32 "
        "{%0,%1,%2,%3}, {%4,%5,%6,%7}, {%8,%9}, {%0,%1,%2,%3};"
        : "+f"(c[0]), "+f"(c[1]), "+f"(c[2]), "+f"(c[3])
        : "r"(a[0]), "r"(a[1]), "r"(a[2]), "r"(a[3]), "r"(b[0]), "r"(b[1]));
}
__device__ __forceinline__ void cpa16(uint32_t dst, const void* src) {
    asm volatile("cp.async.cg.shared.global [%0], [%1], 16;"
                 :: "r"(dst), "l"(src));
}
__device__ __forceinline__ void cp_commit() {
    asm volatile("cp.async.commit_group;");
}
__device__ __forceinline__ void cp_wait0() {
    asm volatile("cp.async.wait_group 0;" ::: "memory");
}
__device__ __forceinline__ void cp_wait1() {
    asm volatile("cp.async.wait_group 1;" ::: "memory");
}

// ---------------------------------------------------------------------------
// convert: fp32 -> fp16, vectorized x4
// ---------------------------------------------------------------------------
__global__ void convert_kernel(const float* __restrict__ X,
                               __half* __restrict__ H, int n4)
{
    int i = blockIdx.x * blockDim.x + threadIdx.x;
    if (i >= n4) return;
    float4 v = ((const float4*)X)[i];
    __half2 h0 = __floats2half2_rn(v.x, v.y);
    __half2 h1 = __floats2half2_rn(v.z, v.w);
    ((__half2*)H)[2 * i]     = h0;
    ((__half2*)H)[2 * i + 1] = h1;
}

// ---------------------------------------------------------------------------
// merged transpose: all four weights in one launch (grid.z selects tensor)
// ---------------------------------------------------------------------------
__global__ void transpose_all_kernel(
    const float* __restrict__ Wq, const float* __restrict__ Wk,
    const float* __restrict__ Wv, const float* __restrict__ Wo,
    __half* __restrict__ Tq, __half* __restrict__ Tk,
    __half* __restrict__ Tv, __half* __restrict__ To)
{
    const int z = blockIdx.z;
    const float* W;
    __half* Th;
    int N;
    if (z == 0)      { W = Wq; Th = Tq; N = C_; }
    else if (z == 1) { W = Wk; Th = Tk; N = KVD; }
    else if (z == 2) { W = Wv; Th = Tv; N = KVD; }
    else             { W = Wo; Th = To; N = C_; }
    const int K = C_;
    const int n0 = blockIdx.x * 32, k0 = blockIdx.y * 32;
    if (n0 >= N) return;

    __shared__ float t[32][33];
    int tx = threadIdx.x, ty = threadIdx.y;  // 32 x 8
#pragma unroll
    for (int j = 0; j < 4; j++)
        t[ty + 8 * j][tx] = W[(size_t)(k0 + ty + 8 * j) * N + n0 + tx];
    __syncthreads();
#pragma unroll
    for (int j = 0; j < 4; j++)
        Th[(size_t)(n0 + ty + 8 * j) * K + k0 + tx] =
            __float2half(t[tx][ty + 8 * j]);
}

// ---------------------------------------------------------------------------
// Fused QKV projection + RoPE, single-pass fp16; double-buffered smem.
// Grid x: 0-15 Q, 16-19 K, 20-23 V. CTA 128x128, BK=32.  (R14 proven)
// ---------------------------------------------------------------------------
#define SAS   40
#define GBUF  (128 * SAS * 2)
#define GSTG2 (2 * GBUF)
#define GEMM_SMEM (2 * GSTG2)

extern __shared__ char dynsm[];

__global__ __launch_bounds__(256) void qkv_gemm(
    const __half* __restrict__ Ah,
    const __half* __restrict__ Wqh, const __half* __restrict__ Wkh,
    const __half* __restrict__ Wvh,
    __half* __restrict__ Qh, __half* __restrict__ Kh, __half* __restrict__ Vh,
    const int* __restrict__ posp)
{
    const int K = C_;
    const int tid = threadIdx.x;
    const int lane = tid & 31, wid = tid >> 5;
    const int wm = wid & 1, wn = wid >> 1;
    const int m0 = blockIdx.y * 128;
    const int nq = blockIdx.x;

    const __half* Bp;
    int mode;                      // 0=Q(rope) 1=K(rope) 2=V
    if (nq < 16)      { Bp = Wqh + (size_t)nq * 128 * K;        mode = 0; }
    else if (nq < 20) { Bp = Wkh + (size_t)(nq - 16) * 128 * K; mode = 1; }
    else              { Bp = Wvh + (size_t)(nq - 20) * 128 * K; mode = 2; }

    const int ldrow = tid >> 1, ldhalf = tid & 1;
    const __half* gAh = Ah + (size_t)(m0 + ldrow) * K + ldhalf * 16;
    const __half* gBh = Bp + (size_t)ldrow * K + ldhalf * 16;
    char* dsm = dynsm + (ldrow * SAS + ldhalf * 16) * 2;

    const int mid = lane >> 3, rin = lane & 7;
    const uint32_t usm = smem_u32(dynsm);
    const uint32_t aoff =
        ((wm * 64 + (mid & 1) * 8 + rin) * SAS + (mid >> 1) * 8) * 2;
    const uint32_t boff =
        ((wn * 16 + (mid >> 1) * 8 + rin) * SAS + (mid & 1) * 8) * 2;
    const uint32_t uAh = usm + aoff;
    const uint32_t uBh = usm + GBUF + boff;

    float acc[4][4][4];
#pragma unroll
    for (int mt = 0; mt < 4; mt++)
#pragma unroll
        for (int nt = 0; nt < 4; nt++)
#pragma unroll
            for (int j = 0; j < 4; j++) acc[mt][nt][j] = 0.0f;

    uint4 rah[2], rbh[2];

#define GLOAD(k0)                                            \
    {                                                        \
        rah[0] = *(const uint4*)(gAh + (k0));                \
        rah[1] = *(const uint4*)(gAh + (k0) + 8);            \
        rbh[0] = *(const uint4*)(gBh + (k0));                \
        rbh[1] = *(const uint4*)(gBh + (k0) + 8);            \
    }
#define SSTORE(stg)                                          \
    {                                                        \
        char* d = dsm + (stg) * GSTG2;                       \
        *(uint4*)(d)             = rah[0];                   \
        *(uint4*)(d + 16)        = rah[1];                   \
        *(uint4*)(d + GBUF)      = rbh[0];                   \
        *(uint4*)(d + GBUF + 16) = rbh[1];                   \
    }

    GLOAD(0);
    SSTORE(0);
    __syncthreads();

    const int nch = K / 32;
    for (int ch = 0; ch < nch; ch++) {
        const bool more = (ch + 1 < nch);
        if (more) GLOAD((ch + 1) * 32);
        const uint32_t so = (ch & 1) * GSTG2;

#pragma unroll
        for (int ks = 0; ks < 2; ks++) {
            uint32_t fah[4][4], fbh[2][4];
#pragma unroll
            for (int mt = 0; mt < 4; mt++)
                ldsm4(fah[mt], uAh + so + mt * (16 * SAS * 2) + ks * 32);
            ldsm4(fbh[0], uBh + so + ks * 32);
            ldsm4(fbh[1], uBh + so + 64 * (SAS * 2) + ks * 32);
#pragma unroll
            for (int mt = 0; mt < 4; mt++)
#pragma unroll
                for (int nt = 0; nt < 4; nt++)
                    mma16816h(acc[mt][nt], fah[mt], &fbh[nt >> 1][(nt & 1) * 2]);
        }
        if (more) {
            SSTORE((ch + 1) & 1);
            __syncthreads();
        }
    }
#undef GLOAD
#undef SSTORE

    const int g = lane >> 2, tg = lane & 3;

    if (mode == 2) {
        const int coff = (nq - 20) * 128;
#pragma unroll
        for (int mt = 0; mt < 4; mt++) {
            const int r0 = m0 + wm * 64 + mt * 16 + g;
#pragma unroll
            for (int nt = 0; nt < 4; nt++) {
                const int c = wn * 16 + (nt & 1) * 8 + ((nt & 2) ? 64 : 0) + tg * 2;
                __half2 h0 = __floats2half2_rn(acc[mt][nt][0], acc[mt][nt][1]);
                __half2 h1 = __floats2half2_rn(acc[mt][nt][2], acc[mt][nt][3]);
                *(uint32_t*)(Vh + (size_t)r0 * KVD + coff + c)       = *(uint32_t*)&h0;
                *(uint32_t*)(Vh + (size_t)(r0 + 8) * KVD + coff + c) = *(uint32_t*)&h1;
            }
        }
        return;
    }

    // Q/K: RoPE on accumulator pairs (nt, nt+2) = cols (c, c+64)
    const int posv = posp[0];
    const float LN1E4_128 = 9.210340371976184f / 128.0f;
#pragma unroll
    for (int mt = 0; mt < 4; mt++) {
        const int mr = m0 + wm * 64 + mt * 16 + g;
#pragma unroll
        for (int nt = 0; nt < 2; nt++) {
            const int c = wn * 16 + nt * 8 + tg * 2;
            const float f1 = __expf(-(float)(2 * (c >> 1)) * LN1E4_128);
            const float f2 = f1 * 0.01f;
#pragma unroll
            for (int rj = 0; rj < 2; rj++) {
                const int row = mr + rj * 8;
                const float pos = (float)(posv + (row & (T_ - 1)));
                const float a1 = pos * f1, a2 = pos * f2;
                const float c1 = cosf(a1), s1 = sinf(a1);
                const float c2 = cosf(a2), s2 = sinf(a2);
                float o1[2], o2[2];
#pragma unroll
                for (int jj = 0; jj < 2; jj++) {
                    const float x1 = acc[mt][nt][rj * 2 + jj];
                    const float x2 = acc[mt][nt + 2][rj * 2 + jj];
                    o1[jj] = x1 * c1 - x2 * s1;
                    o2[jj] = x2 * c2 + x1 * s2;
                }
                __half2 hi1 = __floats2half2_rn(o1[0], o1[1]);
                __half2 hi2 = __floats2half2_rn(o2[0], o2[1]);
                if (mode == 0) {
                    size_t base = (size_t)row * C_ + nq * 128 + c;
                    *(uint32_t*)(Qh + base)      = *(uint32_t*)&hi1;
                    *(uint32_t*)(Qh + base + 64) = *(uint32_t*)&hi2;
                } else {
                    size_t base = (size_t)row * KVD + (nq - 16) * 128 + c;
                    *(uint32_t*)(Kh + base)      = *(uint32_t*)&hi1;
                    *(uint32_t*)(Kh + base + 64) = *(uint32_t*)&hi2;
                }
            }
        }
    }
}

// ---------------------------------------------------------------------------
// fp16 single-pass Wo GEMM; double-buffered smem (R11 proven)
// ---------------------------------------------------------------------------
__global__ __launch_bounds__(256) void gemm_mma1(
    const __half* __restrict__ Ah, const __half* __restrict__ Bh,
    float* __restrict__ C, int N, int K)
{
    const int tid = threadIdx.x;
    const int lane = tid & 31, wid = tid >> 5;
    const int wm = wid & 1, wn = wid >> 1;
    const int m0 = blockIdx.y * 128, n0 = blockIdx.x * 128;

    const int ldrow = tid >> 1, ldhalf = tid & 1;
    const __half* gAh = Ah + (size_t)(m0 + ldrow) * K + ldhalf * 16;
    const __half* gBh = Bh + (size_t)(n0 + ldrow) * K + ldhalf * 16;
    char* dsm = dynsm + (ldrow * SAS + ldhalf * 16) * 2;

    const int mid = lane >> 3, rin = lane & 7;
    const uint32_t usm = smem_u32(dynsm);
    const uint32_t aoff =
        ((wm * 64 + (mid & 1) * 8 + rin) * SAS + (mid >> 1) * 8) * 2;
    const uint32_t boff =
        ((wn * 32 + (mid >> 1) * 8 + rin) * SAS + (mid & 1) * 8) * 2;
    const uint32_t uAh = usm + aoff;
    const uint32_t uBh = usm + GBUF + boff;

    float acc[4][4][4];
#pragma unroll
    for (int mt = 0; mt < 4; mt++)
#pragma unroll
        for (int nt = 0; nt < 4; nt++)
#pragma unroll
            for (int j = 0; j < 4; j++) acc[mt][nt][j] = 0.0f;

    uint4 rah[2], rbh[2];

#define GLOAD(k0)                                            \
    {                                                        \
        rah[0] = *(const uint4*)(gAh + (k0));                \
        rah[1] = *(const uint4*)(gAh + (k0) + 8);            \
        rbh[0] = *(const uint4*)(gBh + (k0));                \
        rbh[1] = *(const uint4*)(gBh + (k0) + 8);            \
    }
#define SSTORE(stg)                                          \
    {                                                        \
        char* d = dsm + (stg) * GSTG2;                       \
        *(uint4*)(d)             = rah[0];                   \
        *(uint4*)(d + 16)        = rah[1];                   \
        *(uint4*)(d + GBUF)      = rbh[0];                   \
        *(uint4*)(d + GBUF + 16) = rbh[1];                   \
    }

    GLOAD(0);
    SSTORE(0);
    __syncthreads();

    const int nch = K / 32;
    for (int ch = 0; ch < nch; ch++) {
        const bool more = (ch + 1 < nch);
        if (more) GLOAD((ch + 1) * 32);
        const uint32_t so = (ch & 1) * GSTG2;

#pragma unroll
        for (int ks = 0; ks < 2; ks++) {
            uint32_t fah[4][4], fbh[2][4];
#pragma unroll
            for (int mt = 0; mt < 4; mt++)
                ldsm4(fah[mt], uAh + so + mt * (16 * SAS * 2) + ks * 32);
#pragma unroll
            for (int np = 0; np < 2; np++)
                ldsm4(fbh[np], uBh + so + np * (16 * SAS * 2) + ks * 32);
#pragma unroll
            for (int mt = 0; mt < 4; mt++)
#pragma unroll
                for (int nt = 0; nt < 4; nt++)
                    mma16816h(acc[mt][nt], fah[mt], &fbh[nt >> 1][(nt & 1) * 2]);
        }
        if (more) {
            SSTORE((ch + 1) & 1);
            __syncthreads();
        }
    }
#undef GLOAD
#undef SSTORE

    const int g = lane >> 2, tg = lane & 3;
#pragma unroll
    for (int mt = 0; mt < 4; mt++) {
        const int mrow = m0 + wm * 64 + mt * 16 + g;
#pragma unroll
        for (int nt = 0; nt < 4; nt++) {
            const int ncol = n0 + wn * 32 + nt * 8 + tg * 2;
            float2 v0 = {acc[mt][nt][0], acc[mt][nt][1]};
            float2 v1 = {acc[mt][nt][2], acc[mt][nt][3]};
            *(float2*)(C + (size_t)mrow * N + ncol)       = v0;
            *(float2*)(C + (size_t)(mrow + 8) * N + ncol) = v1;
        }
    }
}

// ---------------------------------------------------------------------------
// Flash attention: 256-thread CTA = TWO heads sharing one KV tile.
// Warps 0-3 -> head 2hy, warps 4-7 -> head 2hy+1 (same kv-head).
// Each warp: 16 q-rows. cp.async double-buffered K/V, single-pass fp16.
// ---------------------------------------------------------------------------
#define SKP 136
#define FSTG (2 * 64 * SKP * 2)      // one stage: Kh + Vh (34816 B)
#define FL_SMEM (2 * FSTG)

__global__ __launch_bounds__(256) void flash_mma(
    const __half* __restrict__ Qh,
    const __half* __restrict__ Khg, const __half* __restrict__ Vhg,
    __half* __restrict__ Yh)
{
    const int tid = threadIdx.x, lane = tid & 31, w = tid >> 5;
    const int qb = blockIdx.x, hy = blockIdx.y, b = blockIdx.z;
    const int h = hy * 2 + (w >> 2);          // this warp's head
    const int kvh = h >> 2;                   // == (hy*2)>>2 for both heads
    const int wh = w & 3;                     // warp-in-head 0..3
    const int g = lane >> 2, tg = lane & 3;
    const int mid = lane >> 3, rin = lane & 7;
    const int qrow0 = qb * 64 + wh * 16;

    uint32_t qh[8][4];
    {
        const __half* Qhb = Qh + ((size_t)b * T_ + qrow0) * C_ + h * HD;
#pragma unroll
        for (int kc = 0; kc < 8; kc++) {
#pragma unroll
            for (int fr = 0; fr < 4; fr++) {
                int r = g + (fr & 1) * 8;
                int c = kc * 16 + tg * 2 + (fr >> 1) * 8;
                qh[kc][fr] = *(const uint32_t*)(Qhb + (size_t)r * C_ + c);
            }
        }
    }

    float o[16][4];
#pragma unroll
    for (int nt = 0; nt < 16; nt++)
#pragma unroll
        for (int j = 0; j < 4; j++) o[nt][j] = 0.0f;
    float m0 = -INFINITY, m1 = -INFINITY, l0 = 0.0f, l1 = 0.0f;

    const float cscale = 0.08838834764831845f;
    const int rg0 = qrow0 + g, rg1 = rg0 + 8;
    const int ktmax = qb + 1;

    const __half* Kh0 = Khg + (size_t)b * T_ * KVD + kvh * HD;
    const __half* Vh0 = Vhg + (size_t)b * T_ * KVD + kvh * HD;

    const uint32_t usm = smem_u32(dynsm);
    const uint32_t uK = usm, uV = usm + 64 * SKP * 2;
    const uint32_t kfrag = (((mid >> 1) * 8 + rin) * SKP + (mid & 1) * 8) * 2;
    const uint32_t vfrag = (((mid & 1) * 8 + rin) * SKP + (mid >> 1) * 8) * 2;

    // 256-thread loader: 4 row-steps x 16B chunks for each of K, V
    const int lr = tid >> 4, lc8 = (tid & 15) << 3;   // row 0..15, col 0..120

#define FLOAD(stg, kt)                                                        \
    {                                                                         \
        const __half* Kt = Kh0 + (size_t)(kt) * 64 * KVD;                     \
        const __half* Vt = Vh0 + (size_t)(kt) * 64 * KVD;                     \
        uint32_t base = usm + (stg) * FSTG;                                   \
        _Pragma("unroll")                                                     \
        for (int it = 0; it < 4; it++) {                                      \
            int r = lr + it * 16;                                             \
            uint32_t so = base + (r * SKP + lc8) * 2;                         \
            cpa16(so,                 Kt + (size_t)r * KVD + lc8);            \
            cpa16(so + 64 * SKP * 2,  Vt + (size_t)r * KVD + lc8);            \
        }                                                                     \
        cp_commit();                                                          \
    }

    FLOAD(0, 0);

    for (int kt = 0; kt < ktmax; kt++) {
        const bool more = (kt + 1 < ktmax);
        if (more) FLOAD((kt + 1) & 1, kt + 1);
        if (more) cp_wait1(); else cp_wait0();
        __syncthreads();

        const uint32_t so = (kt & 1) * FSTG;
        const uint32_t uKh = uK + so, uVh = uV + so;

        {
            const bool needmask = (kt * 64 + 63 > qrow0);

            float s[8][4];
#pragma unroll
            for (int nt = 0; nt < 8; nt++)
#pragma unroll
                for (int j = 0; j < 4; j++) s[nt][j] = 0.0f;

#pragma unroll
            for (int kc = 0; kc < 8; kc++) {
                uint32_t bt[4][4];
#pragma unroll
                for (int nt2 = 0; nt2 < 4; nt2++)
                    ldsm4(bt[nt2], uKh + kfrag + (nt2 * 16 * SKP + kc * 16) * 2);
#pragma unroll
                for (int nt = 0; nt < 8; nt++)
                    mma16816h(s[nt], qh[kc], &bt[nt >> 1][(nt & 1) * 2]);
            }

#pragma unroll
            for (int nt = 0; nt < 8; nt++) {
#pragma unroll
                for (int j = 0; j < 4; j++) s[nt][j] *= cscale;
                if (needmask) {
                    int c0 = kt * 64 + nt * 8 + tg * 2;
                    if (c0 > rg0)     s[nt][0] = -1e30f;
                    if (c0 + 1 > rg0) s[nt][1] = -1e30f;
                    if (c0 > rg1)     s[nt][2] = -1e30f;
                    if (c0 + 1 > rg1) s[nt][3] = -1e30f;
                }
            }

            float mn0 = m0, mn1 = m1;
#pragma unroll
            for (int nt = 0; nt < 8; nt++) {
                mn0 = fmaxf(mn0, fmaxf(s[nt][0], s[nt][1]));
                mn1 = fmaxf(mn1, fmaxf(s[nt][2], s[nt][3]));
            }
            mn0 = fmaxf(mn0, __shfl_xor_sync(0xffffffffu, mn0, 1));
            mn0 = fmaxf(mn0, __shfl_xor_sync(0xffffffffu, mn0, 2));
            mn1 = fmaxf(mn1, __shfl_xor_sync(0xffffffffu, mn1, 1));
            mn1 = fmaxf(mn1, __shfl_xor_sync(0xffffffffu, mn1, 2));
            float fac0 = __expf(m0 - mn0), fac1 = __expf(m1 - mn1);
            m0 = mn0; m1 = mn1;

            uint32_t pa[4][4];
            float ps0 = 0.0f, ps1 = 0.0f;
#pragma unroll
            for (int kk = 0; kk < 4; kk++) {
                int nt = 2 * kk;
                float p00 = __expf(s[nt][0] - m0),     p01 = __expf(s[nt][1] - m0);
                float p02 = __expf(s[nt][2] - m1),     p03 = __expf(s[nt][3] - m1);
                float p10 = __expf(s[nt + 1][0] - m0), p11 = __expf(s[nt + 1][1] - m0);
                float p12 = __expf(s[nt + 1][2] - m1), p13 = __expf(s[nt + 1][3] - m1);
                ps0 += p00 + p01 + p10 + p11;
                ps1 += p02 + p03 + p12 + p13;
                __half2 a0 = __floats2half2_rn(p00, p01);
                __half2 a1 = __floats2half2_rn(p02, p03);
                __half2 a2 = __floats2half2_rn(p10, p11);
                __half2 a3 = __floats2half2_rn(p12, p13);
                pa[kk][0] = *(uint32_t*)&a0;
                pa[kk][1] = *(uint32_t*)&a1;
                pa[kk][2] = *(uint32_t*)&a2;
                pa[kk][3] = *(uint32_t*)&a3;
            }
            l0 = l0 * fac0 + ps0;
            l1 = l1 * fac1 + ps1;

#pragma unroll
            for (int nt = 0; nt < 16; nt++) {
                o[nt][0] *= fac0; o[nt][1] *= fac0;
                o[nt][2] *= fac1; o[nt][3] *= fac1;
            }

#pragma unroll
            for (int kk = 0; kk < 4; kk++) {
                uint32_t vb[8][4];
#pragma unroll
                for (int np = 0; np < 8; np++)
                    ldsm4t(vb[np], uVh + vfrag + (kk * 16 * SKP + np * 16) * 2);
#pragma unroll
                for (int nt = 0; nt < 16; nt++)
                    mma16816h(o[nt], pa[kk], &vb[nt >> 1][(nt & 1) * 2]);
            }
        }
        __syncthreads();
    }
#undef FLOAD

    l0 += __shfl_xor_sync(0xffffffffu, l0, 1);
    l0 += __shfl_xor_sync(0xffffffffu, l0, 2);
    l1 += __shfl_xor_sync(0xffffffffu, l1, 1);
    l1 += __shfl_xor_sync(0xffffffffu, l1, 2);
    float inv0 = 1.0f / l0, inv1 = 1.0f / l1;

    size_t row0 = (size_t)b * T_ + rg0;
    size_t row1 = (size_t)b * T_ + rg1;
#pragma unroll
    for (int nt = 0; nt < 16; nt++) {
        int col = h * HD + nt * 8 + tg * 2;
        __half2 h0 = __floats2half2_rn(o[nt][0] * inv0, o[nt][1] * inv0);
        __half2 h1 = __floats2half2_rn(o[nt][2] * inv1, o[nt][3] * inv1);
        *(uint32_t*)(Yh + row0 * C_ + col) = *(uint32_t*)&h0;
        *(uint32_t*)(Yh + row1 * C_ + col) = *(uint32_t*)&h1;
    }
}

// ---------------------------------------------------------------------------
extern "C" void kernel_launch(void* const* d_in, const int* in_sizes, int n_in,
                              void* d_out, int out_size)
{
    const float* x  = (const float*)d_in[0];
    const float* Wq = (const float*)d_in[1];
    const float* Wk = (const float*)d_in[2];
    const float* Wv = (const float*)d_in[3];
    const float* Wo = (const float*)d_in[4];
    const int*  pos = (const int*)d_in[5];
    float* out = (float*)d_out;

    __half *qh, *kh, *vh;
    cudaGetSymbolAddress((void**)&qh, s_qh);
    cudaGetSymbolAddress((void**)&kh, s_kh);
    cudaGetSymbolAddress((void**)&vh, s_vh);
    __half *xh, *yh, *wqh, *wkh, *wvh, *woh;
    cudaGetSymbolAddress((void**)&xh, s_xh);
    cudaGetSymbolAddress((void**)&yh, s_yh);
    cudaGetSymbolAddress((void**)&wqh, s_wqh);
    cudaGetSymbolAddress((void**)&wkh, s_wkh);
    cudaGetSymbolAddress((void**)&wvh, s_wvh);
    cudaGetSymbolAddress((void**)&woh, s_woh);

    cudaFuncSetAttribute(qkv_gemm, cudaFuncAttributeMaxDynamicSharedMemorySize,
                         GEMM_SMEM);
    cudaFuncSetAttribute(gemm_mma1, cudaFuncAttributeMaxDynamicSharedMemorySize,
                         GEMM_SMEM);
    cudaFuncSetAttribute(flash_mma, cudaFuncAttributeMaxDynamicSharedMemorySize,
                         FL_SMEM);

    {
        int n4 = M_ * C_ / 4;
        convert_kernel<<<(n4 + 255) / 256, 256>>>(x, xh, n4);
    }
    transpose_all_kernel<<<dim3(C_ / 32, C_ / 32, 4), dim3(32, 8)>>>(
        Wq, Wk, Wv, Wo, wqh, wkh, wvh, woh);

    qkv_gemm<<<dim3(24, M_ / 128), 256, GEMM_SMEM>>>(xh, wqh, wkh, wvh,
                                                     qh, kh, vh, pos);

    // two heads (sharing a kv-head) per CTA
    flash_mma<<<dim3(T_ / 64, NH / 2, B_), 256, FL_SMEM>>>(qh, kh, vh, yh);

    gemm_mma1<<<dim3(C_ / 128, M_ / 128), 256, GEMM_SMEM>>>(yh, woh, out, C_, C_);
}

// round 16
// speedup vs baseline: 1.0029x; 1.0029x over previous
#include <cuda_runtime.h>
#include <cuda_fp16.h>
#include <math.h>
#include <stdint.h>

#define B_   4
#define T_   2048
#define C_   2048
#define NH   16
#define NKV  4
#define HD   128
#define KVD  (NKV*HD)   // 512
#define M_   (B_*T_)    // 8192

// ---------------- scratch (__device__ globals; no allocs allowed) ----------
__device__ __half s_qh[(size_t)M_ * C_];
__device__ __half s_kh[(size_t)M_ * KVD];
__device__ __half s_vh[(size_t)M_ * KVD];

__device__ __half s_xh[(size_t)M_ * C_];
__device__ __half s_yh[(size_t)M_ * C_];
__device__ __half s_wqh[(size_t)C_ * C_];
__device__ __half s_wkh[(size_t)KVD * C_];
__device__ __half s_wvh[(size_t)KVD * C_];
__device__ __half s_woh[(size_t)C_ * C_];

// ---------------- helpers ---------------------------------------------------
__device__ __forceinline__ uint32_t smem_u32(const void* p) {
    uint32_t a;
    asm("{ .reg .u64 t; cvta.to.shared.u64 t, %1; cvt.u32.u64 %0, t; }"
        : "=r"(a) : "l"(p));
    return a;
}
__device__ __forceinline__ void ldsm4(uint32_t* r, uint32_t addr) {
    asm volatile("ldmatrix.sync.aligned.m8n8.x4.shared.b16 {%0,%1,%2,%3}, [%4];"
                 : "=r"(r[0]), "=r"(r[1]), "=r"(r[2]), "=r"(r[3]) : "r"(addr));
}
__device__ __forceinline__ void ldsm4t(uint32_t* r, uint32_t addr) {
    asm volatile("ldmatrix.sync.aligned.m8n8.x4.trans.shared.b16 {%0,%1,%2,%3}, [%4];"
                 : "=r"(r[0]), "=r"(r[1]), "=r"(r[2]), "=r"(r[3]) : "r"(addr));
}
__device__ __forceinline__ void mma16816h(float* c, const uint32_t* a,
                                          const uint32_t* b) {
    asm volatile(
        "mma.sync.aligned.m16n8k16.row.col.f32.f16.f16.f32 "
        "{%0,%1,%2,%3}, {%4,%5,%6,%7}, {%8,%9}, {%0,%1,%2,%3};"
        : "+f"(c[0]), "+f"(c[1]), "+f"(c[2]), "+f"(c[3])
        : "r"(a[0]), "r"(a[1]), "r"(a[2]), "r"(a[3]), "r"(b[0]), "r"(b[1]));
}
__device__ __forceinline__ void cpa16(uint32_t dst, const void* src) {
    asm volatile("cp.async.cg.shared.global [%0], [%1], 16;"
                 :: "r"(dst), "l"(src));
}
__device__ __forceinline__ void cp_commit() {
    asm volatile("cp.async.commit_group;");
}
__device__ __forceinline__ void cp_wait0() {
    asm volatile("cp.async.wait_group 0;" ::: "memory");
}
__device__ __forceinline__ void cp_wait1() {
    asm volatile("cp.async.wait_group 1;" ::: "memory");
}

// ---------------------------------------------------------------------------
// convert: fp32 -> fp16, vectorized x4
// ---------------------------------------------------------------------------
__global__ void convert_kernel(const float* __restrict__ X,
                               __half* __restrict__ H, int n4)
{
    int i = blockIdx.x * blockDim.x + threadIdx.x;
    if (i >= n4) return;
    float4 v = ((const float4*)X)[i];
    __half2 h0 = __floats2half2_rn(v.x, v.y);
    __half2 h1 = __floats2half2_rn(v.z, v.w);
    ((__half2*)H)[2 * i]     = h0;
    ((__half2*)H)[2 * i + 1] = h1;
}

// ---------------------------------------------------------------------------
// merged transpose: all four weights in one launch (grid.z selects tensor)
// ---------------------------------------------------------------------------
__global__ void transpose_all_kernel(
    const float* __restrict__ Wq, const float* __restrict__ Wk,
    const float* __restrict__ Wv, const float* __restrict__ Wo,
    __half* __restrict__ Tq, __half* __restrict__ Tk,
    __half* __restrict__ Tv, __half* __restrict__ To)
{
    const int z = blockIdx.z;
    const float* W;
    __half* Th;
    int N;
    if (z == 0)      { W = Wq; Th = Tq; N = C_; }
    else if (z == 1) { W = Wk; Th = Tk; N = KVD; }
    else if (z == 2) { W = Wv; Th = Tv; N = KVD; }
    else             { W = Wo; Th = To; N = C_; }
    const int K = C_;
    const int n0 = blockIdx.x * 32, k0 = blockIdx.y * 32;
    if (n0 >= N) return;

    __shared__ float t[32][33];
    int tx = threadIdx.x, ty = threadIdx.y;  // 32 x 8
#pragma unroll
    for (int j = 0; j < 4; j++)
        t[ty + 8 * j][tx] = W[(size_t)(k0 + ty + 8 * j) * N + n0 + tx];
    __syncthreads();
#pragma unroll
    for (int j = 0; j < 4; j++)
        Th[(size_t)(n0 + ty + 8 * j) * K + k0 + tx] =
            __float2half(t[tx][ty + 8 * j]);
}

// ---------------------------------------------------------------------------
// Fused QKV projection + RoPE, single-pass fp16; double-buffered smem.
// Grid x: 0-15 Q, 16-19 K, 20-23 V. CTA 128x128, BK=32.  (R14 proven)
// ---------------------------------------------------------------------------
#define SAS   40
#define GBUF  (128 * SAS * 2)
#define GSTG2 (2 * GBUF)
#define GEMM_SMEM (2 * GSTG2)

extern __shared__ char dynsm[];

__global__ __launch_bounds__(256) void qkv_gemm(
    const __half* __restrict__ Ah,
    const __half* __restrict__ Wqh, const __half* __restrict__ Wkh,
    const __half* __restrict__ Wvh,
    __half* __restrict__ Qh, __half* __restrict__ Kh, __half* __restrict__ Vh,
    const int* __restrict__ posp)
{
    const int K = C_;
    const int tid = threadIdx.x;
    const int lane = tid & 31, wid = tid >> 5;
    const int wm = wid & 1, wn = wid >> 1;
    const int m0 = blockIdx.y * 128;
    const int nq = blockIdx.x;

    const __half* Bp;
    int mode;                      // 0=Q(rope) 1=K(rope) 2=V
    if (nq < 16)      { Bp = Wqh + (size_t)nq * 128 * K;        mode = 0; }
    else if (nq < 20) { Bp = Wkh + (size_t)(nq - 16) * 128 * K; mode = 1; }
    else              { Bp = Wvh + (size_t)(nq - 20) * 128 * K; mode = 2; }

    const int ldrow = tid >> 1, ldhalf = tid & 1;
    const __half* gAh = Ah + (size_t)(m0 + ldrow) * K + ldhalf * 16;
    const __half* gBh = Bp + (size_t)ldrow * K + ldhalf * 16;
    char* dsm = dynsm + (ldrow * SAS + ldhalf * 16) * 2;

    const int mid = lane >> 3, rin = lane & 7;
    const uint32_t usm = smem_u32(dynsm);
    const uint32_t aoff =
        ((wm * 64 + (mid & 1) * 8 + rin) * SAS + (mid >> 1) * 8) * 2;
    const uint32_t boff =
        ((wn * 16 + (mid >> 1) * 8 + rin) * SAS + (mid & 1) * 8) * 2;
    const uint32_t uAh = usm + aoff;
    const uint32_t uBh = usm + GBUF + boff;

    float acc[4][4][4];
#pragma unroll
    for (int mt = 0; mt < 4; mt++)
#pragma unroll
        for (int nt = 0; nt < 4; nt++)
#pragma unroll
            for (int j = 0; j < 4; j++) acc[mt][nt][j] = 0.0f;

    uint4 rah[2], rbh[2];

#define GLOAD(k0)                                            \
    {                                                        \
        rah[0] = *(const uint4*)(gAh + (k0));                \
        rah[1] = *(const uint4*)(gAh + (k0) + 8);            \
        rbh[0] = *(const uint4*)(gBh + (k0));                \
        rbh[1] = *(const uint4*)(gBh + (k0) + 8);            \
    }
#define SSTORE(stg)                                          \
    {                                                        \
        char* d = dsm + (stg) * GSTG2;                       \
        *(uint4*)(d)             = rah[0];                   \
        *(uint4*)(d + 16)        = rah[1];                   \
        *(uint4*)(d + GBUF)      = rbh[0];                   \
        *(uint4*)(d + GBUF + 16) = rbh[1];                   \
    }

    GLOAD(0);
    SSTORE(0);
    __syncthreads();

    const int nch = K / 32;
    for (int ch = 0; ch < nch; ch++) {
        const bool more = (ch + 1 < nch);
        if (more) GLOAD((ch + 1) * 32);
        const uint32_t so = (ch & 1) * GSTG2;

#pragma unroll
        for (int ks = 0; ks < 2; ks++) {
            uint32_t fah[4][4], fbh[2][4];
#pragma unroll
            for (int mt = 0; mt < 4; mt++)
                ldsm4(fah[mt], uAh + so + mt * (16 * SAS * 2) + ks * 32);
            ldsm4(fbh[0], uBh + so + ks * 32);
            ldsm4(fbh[1], uBh + so + 64 * (SAS * 2) + ks * 32);
#pragma unroll
            for (int mt = 0; mt < 4; mt++)
#pragma unroll
                for (int nt = 0; nt < 4; nt++)
                    mma16816h(acc[mt][nt], fah[mt], &fbh[nt >> 1][(nt & 1) * 2]);
        }
        if (more) {
            SSTORE((ch + 1) & 1);
            __syncthreads();
        }
    }
#undef GLOAD
#undef SSTORE

    const int g = lane >> 2, tg = lane & 3;

    if (mode == 2) {
        const int coff = (nq - 20) * 128;
#pragma unroll
        for (int mt = 0; mt < 4; mt++) {
            const int r0 = m0 + wm * 64 + mt * 16 + g;
#pragma unroll
            for (int nt = 0; nt < 4; nt++) {
                const int c = wn * 16 + (nt & 1) * 8 + ((nt & 2) ? 64 : 0) + tg * 2;
                __half2 h0 = __floats2half2_rn(acc[mt][nt][0], acc[mt][nt][1]);
                __half2 h1 = __floats2half2_rn(acc[mt][nt][2], acc[mt][nt][3]);
                *(uint32_t*)(Vh + (size_t)r0 * KVD + coff + c)       = *(uint32_t*)&h0;
                *(uint32_t*)(Vh + (size_t)(r0 + 8) * KVD + coff + c) = *(uint32_t*)&h1;
            }
        }
        return;
    }

    // Q/K: RoPE on accumulator pairs (nt, nt+2) = cols (c, c+64)
    const int posv = posp[0];
    const float LN1E4_128 = 9.210340371976184f / 128.0f;
#pragma unroll
    for (int mt = 0; mt < 4; mt++) {
        const int mr = m0 + wm * 64 + mt * 16 + g;
#pragma unroll
        for (int nt = 0; nt < 2; nt++) {
            const int c = wn * 16 + nt * 8 + tg * 2;
            const float f1 = __expf(-(float)(2 * (c >> 1)) * LN1E4_128);
            const float f2 = f1 * 0.01f;
#pragma unroll
            for (int rj = 0; rj < 2; rj++) {
                const int row = mr + rj * 8;
                const float pos = (float)(posv + (row & (T_ - 1)));
                const float a1 = pos * f1, a2 = pos * f2;
                const float c1 = cosf(a1), s1 = sinf(a1);
                const float c2 = cosf(a2), s2 = sinf(a2);
                float o1[2], o2[2];
#pragma unroll
                for (int jj = 0; jj < 2; jj++) {
                    const float x1 = acc[mt][nt][rj * 2 + jj];
                    const float x2 = acc[mt][nt + 2][rj * 2 + jj];
                    o1[jj] = x1 * c1 - x2 * s1;
                    o2[jj] = x2 * c2 + x1 * s2;
                }
                __half2 hi1 = __floats2half2_rn(o1[0], o1[1]);
                __half2 hi2 = __floats2half2_rn(o2[0], o2[1]);
                if (mode == 0) {
                    size_t base = (size_t)row * C_ + nq * 128 + c;
                    *(uint32_t*)(Qh + base)      = *(uint32_t*)&hi1;
                    *(uint32_t*)(Qh + base + 64) = *(uint32_t*)&hi2;
                } else {
                    size_t base = (size_t)row * KVD + (nq - 16) * 128 + c;
                    *(uint32_t*)(Kh + base)      = *(uint32_t*)&hi1;
                    *(uint32_t*)(Kh + base + 64) = *(uint32_t*)&hi2;
                }
            }
        }
    }
}

// ---------------------------------------------------------------------------
// fp16 single-pass Wo GEMM; double-buffered smem (R11 proven)
// ---------------------------------------------------------------------------
__global__ __launch_bounds__(256) void gemm_mma1(
    const __half* __restrict__ Ah, const __half* __restrict__ Bh,
    float* __restrict__ C, int N, int K)
{
    const int tid = threadIdx.x;
    const int lane = tid & 31, wid = tid >> 5;
    const int wm = wid & 1, wn = wid >> 1;
    const int m0 = blockIdx.y * 128, n0 = blockIdx.x * 128;

    const int ldrow = tid >> 1, ldhalf = tid & 1;
    const __half* gAh = Ah + (size_t)(m0 + ldrow) * K + ldhalf * 16;
    const __half* gBh = Bh + (size_t)(n0 + ldrow) * K + ldhalf * 16;
    char* dsm = dynsm + (ldrow * SAS + ldhalf * 16) * 2;

    const int mid = lane >> 3, rin = lane & 7;
    const uint32_t usm = smem_u32(dynsm);
    const uint32_t aoff =
        ((wm * 64 + (mid & 1) * 8 + rin) * SAS + (mid >> 1) * 8) * 2;
    const uint32_t boff =
        ((wn * 32 + (mid >> 1) * 8 + rin) * SAS + (mid & 1) * 8) * 2;
    const uint32_t uAh = usm + aoff;
    const uint32_t uBh = usm + GBUF + boff;

    float acc[4][4][4];
#pragma unroll
    for (int mt = 0; mt < 4; mt++)
#pragma unroll
        for (int nt = 0; nt < 4; nt++)
#pragma unroll
            for (int j = 0; j < 4; j++) acc[mt][nt][j] = 0.0f;

    uint4 rah[2], rbh[2];

#define GLOAD(k0)                                            \
    {                                                        \
        rah[0] = *(const uint4*)(gAh + (k0));                \
        rah[1] = *(const uint4*)(gAh + (k0) + 8);            \
        rbh[0] = *(const uint4*)(gBh + (k0));                \
        rbh[1] = *(const uint4*)(gBh + (k0) + 8);            \
    }
#define SSTORE(stg)                                          \
    {                                                        \
        char* d = dsm + (stg) * GSTG2;                       \
        *(uint4*)(d)             = rah[0];                   \
        *(uint4*)(d + 16)        = rah[1];                   \
        *(uint4*)(d + GBUF)      = rbh[0];                   \
        *(uint4*)(d + GBUF + 16) = rbh[1];                   \
    }

    GLOAD(0);
    SSTORE(0);
    __syncthreads();

    const int nch = K / 32;
    for (int ch = 0; ch < nch; ch++) {
        const bool more = (ch + 1 < nch);
        if (more) GLOAD((ch + 1) * 32);
        const uint32_t so = (ch & 1) * GSTG2;

#pragma unroll
        for (int ks = 0; ks < 2; ks++) {
            uint32_t fah[4][4], fbh[2][4];
#pragma unroll
            for (int mt = 0; mt < 4; mt++)
                ldsm4(fah[mt], uAh + so + mt * (16 * SAS * 2) + ks * 32);
#pragma unroll
            for (int np = 0; np < 2; np++)
                ldsm4(fbh[np], uBh + so + np * (16 * SAS * 2) + ks * 32);
#pragma unroll
            for (int mt = 0; mt < 4; mt++)
#pragma unroll
                for (int nt = 0; nt < 4; nt++)
                    mma16816h(acc[mt][nt], fah[mt], &fbh[nt >> 1][(nt & 1) * 2]);
        }
        if (more) {
            SSTORE((ch + 1) & 1);
            __syncthreads();
        }
    }
#undef GLOAD
#undef SSTORE

    const int g = lane >> 2, tg = lane & 3;
#pragma unroll
    for (int mt = 0; mt < 4; mt++) {
        const int mrow = m0 + wm * 64 + mt * 16 + g;
#pragma unroll
        for (int nt = 0; nt < 4; nt++) {
            const int ncol = n0 + wn * 32 + nt * 8 + tg * 2;
            float2 v0 = {acc[mt][nt][0], acc[mt][nt][1]};
            float2 v1 = {acc[mt][nt][2], acc[mt][nt][3]};
            *(float2*)(C + (size_t)mrow * N + ncol)       = v0;
            *(float2*)(C + (size_t)(mrow + 8) * N + ncol) = v1;
        }
    }
}

// ---------------------------------------------------------------------------
// Flash attention (R14 structure): 128-thread CTA (4 warps x 16 rows = 64 q),
// cp.async double-buffered K/V, single-pass fp16 QK and PV.
// __launch_bounds__(128, 3): cap regs ~168 so THREE CTAs (12 warps) co-reside.
// ---------------------------------------------------------------------------
#define SKP 136
#define FSTG (2 * 64 * SKP * 2)      // one stage: Kh + Vh (34816 B)
#define FL_SMEM (2 * FSTG)

__global__ __launch_bounds__(128, 3) void flash_mma(
    const __half* __restrict__ Qh,
    const __half* __restrict__ Khg, const __half* __restrict__ Vhg,
    __half* __restrict__ Yh)
{
    const int tid = threadIdx.x, lane = tid & 31, w = tid >> 5;
    const int qb = blockIdx.x, h = blockIdx.y, b = blockIdx.z;
    const int kvh = h >> 2;
    const int g = lane >> 2, tg = lane & 3;
    const int mid = lane >> 3, rin = lane & 7;
    const int qrow0 = qb * 64 + w * 16;

    uint32_t qh[8][4];
    {
        const __half* Qhb = Qh + ((size_t)b * T_ + qrow0) * C_ + h * HD;
#pragma unroll
        for (int kc = 0; kc < 8; kc++) {
#pragma unroll
            for (int fr = 0; fr < 4; fr++) {
                int r = g + (fr & 1) * 8;
                int c = kc * 16 + tg * 2 + (fr >> 1) * 8;
                qh[kc][fr] = *(const uint32_t*)(Qhb + (size_t)r * C_ + c);
            }
        }
    }

    float o[16][4];
#pragma unroll
    for (int nt = 0; nt < 16; nt++)
#pragma unroll
        for (int j = 0; j < 4; j++) o[nt][j] = 0.0f;
    float m0 = -INFINITY, m1 = -INFINITY, l0 = 0.0f, l1 = 0.0f;

    const float cscale = 0.08838834764831845f;
    const int rg0 = qrow0 + g, rg1 = rg0 + 8;
    const int ktmax = qb + 1;

    const __half* Kh0 = Khg + (size_t)b * T_ * KVD + kvh * HD;
    const __half* Vh0 = Vhg + (size_t)b * T_ * KVD + kvh * HD;

    const uint32_t usm = smem_u32(dynsm);
    const uint32_t uK = usm, uV = usm + 64 * SKP * 2;
    const uint32_t kfrag = (((mid >> 1) * 8 + rin) * SKP + (mid & 1) * 8) * 2;
    const uint32_t vfrag = (((mid & 1) * 8 + rin) * SKP + (mid >> 1) * 8) * 2;

    const int lr = tid >> 4, lc8 = (tid & 15) << 3;

#define FLOAD(stg, kt)                                                        \
    {                                                                         \
        const __half* Kt = Kh0 + (size_t)(kt) * 64 * KVD;                     \
        const __half* Vt = Vh0 + (size_t)(kt) * 64 * KVD;                     \
        uint32_t base = usm + (stg) * FSTG;                                   \
        _Pragma("unroll")                                                     \
        for (int it = 0; it < 8; it++) {                                      \
            int r = lr + it * 8;                                              \
            uint32_t so = base + (r * SKP + lc8) * 2;                         \
            cpa16(so,                 Kt + (size_t)r * KVD + lc8);            \
            cpa16(so + 64 * SKP * 2,  Vt + (size_t)r * KVD + lc8);            \
        }                                                                     \
        cp_commit();                                                          \
    }

    FLOAD(0, 0);

    for (int kt = 0; kt < ktmax; kt++) {
        const bool more = (kt + 1 < ktmax);
        if (more) FLOAD((kt + 1) & 1, kt + 1);
        if (more) cp_wait1(); else cp_wait0();
        __syncthreads();

        const uint32_t so = (kt & 1) * FSTG;
        const uint32_t uKh = uK + so, uVh = uV + so;

        {
            const bool needmask = (kt * 64 + 63 > qrow0);

            float s[8][4];
#pragma unroll
            for (int nt = 0; nt < 8; nt++)
#pragma unroll
                for (int j = 0; j < 4; j++) s[nt][j] = 0.0f;

#pragma unroll
            for (int kc = 0; kc < 8; kc++) {
                uint32_t bt[4][4];
#pragma unroll
                for (int nt2 = 0; nt2 < 4; nt2++)
                    ldsm4(bt[nt2], uKh + kfrag + (nt2 * 16 * SKP + kc * 16) * 2);
#pragma unroll
                for (int nt = 0; nt < 8; nt++)
                    mma16816h(s[nt], qh[kc], &bt[nt >> 1][(nt & 1) * 2]);
            }

#pragma unroll
            for (int nt = 0; nt < 8; nt++) {
#pragma unroll
                for (int j = 0; j < 4; j++) s[nt][j] *= cscale;
                if (needmask) {
                    int c0 = kt * 64 + nt * 8 + tg * 2;
                    if (c0 > rg0)     s[nt][0] = -1e30f;
                    if (c0 + 1 > rg0) s[nt][1] = -1e30f;
                    if (c0 > rg1)     s[nt][2] = -1e30f;
                    if (c0 + 1 > rg1) s[nt][3] = -1e30f;
                }
            }

            float mn0 = m0, mn1 = m1;
#pragma unroll
            for (int nt = 0; nt < 8; nt++) {
                mn0 = fmaxf(mn0, fmaxf(s[nt][0], s[nt][1]));
                mn1 = fmaxf(mn1, fmaxf(s[nt][2], s[nt][3]));
            }
            mn0 = fmaxf(mn0, __shfl_xor_sync(0xffffffffu, mn0, 1));
            mn0 = fmaxf(mn0, __shfl_xor_sync(0xffffffffu, mn0, 2));
            mn1 = fmaxf(mn1, __shfl_xor_sync(0xffffffffu, mn1, 1));
            mn1 = fmaxf(mn1, __shfl_xor_sync(0xffffffffu, mn1, 2));
            float fac0 = __expf(m0 - mn0), fac1 = __expf(m1 - mn1);
            m0 = mn0; m1 = mn1;

            uint32_t pa[4][4];
            float ps0 = 0.0f, ps1 = 0.0f;
#pragma unroll
            for (int kk = 0; kk < 4; kk++) {
                int nt = 2 * kk;
                float p00 = __expf(s[nt][0] - m0),     p01 = __expf(s[nt][1] - m0);
                float p02 = __expf(s[nt][2] - m1),     p03 = __expf(s[nt][3] - m1);
                float p10 = __expf(s[nt + 1][0] - m0), p11 = __expf(s[nt + 1][1] - m0);
                float p12 = __expf(s[nt + 1][2] - m1), p13 = __expf(s[nt + 1][3] - m1);
                ps0 += p00 + p01 + p10 + p11;
                ps1 += p02 + p03 + p12 + p13;
                __half2 a0 = __floats2half2_rn(p00, p01);
                __half2 a1 = __floats2half2_rn(p02, p03);
                __half2 a2 = __floats2half2_rn(p10, p11);
                __half2 a3 = __floats2half2_rn(p12, p13);
                pa[kk][0] = *(uint32_t*)&a0;
                pa[kk][1] = *(uint32_t*)&a1;
                pa[kk][2] = *(uint32_t*)&a2;
                pa[kk][3] = *(uint32_t*)&a3;
            }
            l0 = l0 * fac0 + ps0;
            l1 = l1 * fac1 + ps1;

#pragma unroll
            for (int nt = 0; nt < 16; nt++) {
                o[nt][0] *= fac0; o[nt][1] *= fac0;
                o[nt][2] *= fac1; o[nt][3] *= fac1;
            }

#pragma unroll
            for (int kk = 0; kk < 4; kk++) {
                uint32_t vb[8][4];
#pragma unroll
                for (int np = 0; np < 8; np++)
                    ldsm4t(vb[np], uVh + vfrag + (kk * 16 * SKP + np * 16) * 2);
#pragma unroll
                for (int nt = 0; nt < 16; nt++)
                    mma16816h(o[nt], pa[kk], &vb[nt >> 1][(nt & 1) * 2]);
            }
        }
        __syncthreads();
    }
#undef FLOAD

    l0 += __shfl_xor_sync(0xffffffffu, l0, 1);
    l0 += __shfl_xor_sync(0xffffffffu, l0, 2);
    l1 += __shfl_xor_sync(0xffffffffu, l1, 1);
    l1 += __shfl_xor_sync(0xffffffffu, l1, 2);
    float inv0 = 1.0f / l0, inv1 = 1.0f / l1;

    size_t row0 = (size_t)b * T_ + rg0;
    size_t row1 = (size_t)b * T_ + rg1;
#pragma unroll
    for (int nt = 0; nt < 16; nt++) {
        int col = h * HD + nt * 8 + tg * 2;
        __half2 h0 = __floats2half2_rn(o[nt][0] * inv0, o[nt][1] * inv0);
        __half2 h1 = __floats2half2_rn(o[nt][2] * inv1, o[nt][3] * inv1);
        *(uint32_t*)(Yh + row0 * C_ + col) = *(uint32_t*)&h0;
        *(uint32_t*)(Yh + row1 * C_ + col) = *(uint32_t*)&h1;
    }
}

// ---------------------------------------------------------------------------
extern "C" void kernel_launch(void* const* d_in, const int* in_sizes, int n_in,
                              void* d_out, int out_size)
{
    const float* x  = (const float*)d_in[0];
    const float* Wq = (const float*)d_in[1];
    const float* Wk = (const float*)d_in[2];
    const float* Wv = (const float*)d_in[3];
    const float* Wo = (const float*)d_in[4];
    const int*  pos = (const int*)d_in[5];
    float* out = (float*)d_out;

    __half *qh, *kh, *vh;
    cudaGetSymbolAddress((void**)&qh, s_qh);
    cudaGetSymbolAddress((void**)&kh, s_kh);
    cudaGetSymbolAddress((void**)&vh, s_vh);
    __half *xh, *yh, *wqh, *wkh, *wvh, *woh;
    cudaGetSymbolAddress((void**)&xh, s_xh);
    cudaGetSymbolAddress((void**)&yh, s_yh);
    cudaGetSymbolAddress((void**)&wqh, s_wqh);
    cudaGetSymbolAddress((void**)&wkh, s_wkh);
    cudaGetSymbolAddress((void**)&wvh, s_wvh);
    cudaGetSymbolAddress((void**)&woh, s_woh);

    cudaFuncSetAttribute(qkv_gemm, cudaFuncAttributeMaxDynamicSharedMemorySize,
                         GEMM_SMEM);
    cudaFuncSetAttribute(gemm_mma1, cudaFuncAttributeMaxDynamicSharedMemorySize,
                         GEMM_SMEM);
    cudaFuncSetAttribute(flash_mma, cudaFuncAttributeMaxDynamicSharedMemorySize,
                         FL_SMEM);

    {
        int n4 = M_ * C_ / 4;
        convert_kernel<<<(n4 + 255) / 256, 256>>>(x, xh, n4);
    }
    transpose_all_kernel<<<dim3(C_ / 32, C_ / 32, 4), dim3(32, 8)>>>(
        Wq, Wk, Wv, Wo, wqh, wkh, wvh, woh);

    qkv_gemm<<<dim3(24, M_ / 128), 256, GEMM_SMEM>>>(xh, wqh, wkh, wvh,
                                                     qh, kh, vh, pos);

    flash_mma<<<dim3(T_ / 64, NH, B_), 128, FL_SMEM>>>(qh, kh, vh, yh);

    gemm_mma1<<<dim3(C_ / 128, M_ / 128), 256, GEMM_SMEM>>>(yh, woh, out, C_, C_);
}

// round 17
// speedup vs baseline: 1.0211x; 1.0182x over previous
#include <cuda_runtime.h>
#include <cuda_fp16.h>
#include <math.h>
#include <stdint.h>

#define B_   4
#define T_   2048
#define C_   2048
#define NH   16
#define NKV  4
#define HD   128
#define KVD  (NKV*HD)   // 512
#define M_   (B_*T_)    // 8192

// ---------------- scratch (__device__ globals; no allocs allowed) ----------
__device__ __half s_qh[(size_t)M_ * C_];
__device__ __half s_kh[(size_t)M_ * KVD];
__device__ __half s_vh[(size_t)M_ * KVD];

__device__ __half s_xh[(size_t)M_ * C_];
__device__ __half s_yh[(size_t)M_ * C_];
__device__ __half s_wqh[(size_t)C_ * C_];
__device__ __half s_wkh[(size_t)KVD * C_];
__device__ __half s_wvh[(size_t)KVD * C_];
__device__ __half s_woh[(size_t)C_ * C_];

// ---------------- helpers ---------------------------------------------------
__device__ __forceinline__ uint32_t smem_u32(const void* p) {
    uint32_t a;
    asm("{ .reg .u64 t; cvta.to.shared.u64 t, %1; cvt.u32.u64 %0, t; }"
        : "=r"(a) : "l"(p));
    return a;
}
__device__ __forceinline__ void ldsm4(uint32_t* r, uint32_t addr) {
    asm volatile("ldmatrix.sync.aligned.m8n8.x4.shared.b16 {%0,%1,%2,%3}, [%4];"
                 : "=r"(r[0]), "=r"(r[1]), "=r"(r[2]), "=r"(r[3]) : "r"(addr));
}
__device__ __forceinline__ void ldsm4t(uint32_t* r, uint32_t addr) {
    asm volatile("ldmatrix.sync.aligned.m8n8.x4.trans.shared.b16 {%0,%1,%2,%3}, [%4];"
                 : "=r"(r[0]), "=r"(r[1]), "=r"(r[2]), "=r"(r[3]) : "r"(addr));
}
__device__ __forceinline__ void mma16816h(float* c, const uint32_t* a,
                                          const uint32_t* b) {
    asm volatile(
        "mma.sync.aligned.m16n8k16.row.col.f32.f16.f16.f32 "
        "{%0,%1,%2,%3}, {%4,%5,%6,%7}, {%8,%9}, {%0,%1,%2,%3};"
        : "+f"(c[0]), "+f"(c[1]), "+f"(c[2]), "+f"(c[3])
        : "r"(a[0]), "r"(a[1]), "r"(a[2]), "r"(a[3]), "r"(b[0]), "r"(b[1]));
}
__device__ __forceinline__ void cpa16(uint32_t dst, const void* src) {
    asm volatile("cp.async.cg.shared.global [%0], [%1], 16;"
                 :: "r"(dst), "l"(src));
}
__device__ __forceinline__ void cp_commit() {
    asm volatile("cp.async.commit_group;");
}
__device__ __forceinline__ void cp_wait0() {
    asm volatile("cp.async.wait_group 0;" ::: "memory");
}
__device__ __forceinline__ void cp_wait1() {
    asm volatile("cp.async.wait_group 1;" ::: "memory");
}

// ---------------------------------------------------------------------------
// convert: fp32 -> fp16, vectorized x4
// ---------------------------------------------------------------------------
__global__ void convert_kernel(const float* __restrict__ X,
                               __half* __restrict__ H, int n4)
{
    int i = blockIdx.x * blockDim.x + threadIdx.x;
    if (i >= n4) return;
    float4 v = ((const float4*)X)[i];
    __half2 h0 = __floats2half2_rn(v.x, v.y);
    __half2 h1 = __floats2half2_rn(v.z, v.w);
    ((__half2*)H)[2 * i]     = h0;
    ((__half2*)H)[2 * i + 1] = h1;
}

// ---------------------------------------------------------------------------
// merged transpose: all four weights in one launch (grid.z selects tensor)
// ---------------------------------------------------------------------------
__global__ void transpose_all_kernel(
    const float* __restrict__ Wq, const float* __restrict__ Wk,
    const float* __restrict__ Wv, const float* __restrict__ Wo,
    __half* __restrict__ Tq, __half* __restrict__ Tk,
    __half* __restrict__ Tv, __half* __restrict__ To)
{
    const int z = blockIdx.z;
    const float* W;
    __half* Th;
    int N;
    if (z == 0)      { W = Wq; Th = Tq; N = C_; }
    else if (z == 1) { W = Wk; Th = Tk; N = KVD; }
    else if (z == 2) { W = Wv; Th = Tv; N = KVD; }
    else             { W = Wo; Th = To; N = C_; }
    const int K = C_;
    const int n0 = blockIdx.x * 32, k0 = blockIdx.y * 32;
    if (n0 >= N) return;

    __shared__ float t[32][33];
    int tx = threadIdx.x, ty = threadIdx.y;  // 32 x 8
#pragma unroll
    for (int j = 0; j < 4; j++)
        t[ty + 8 * j][tx] = W[(size_t)(k0 + ty + 8 * j) * N + n0 + tx];
    __syncthreads();
#pragma unroll
    for (int j = 0; j < 4; j++)
        Th[(size_t)(n0 + ty + 8 * j) * K + k0 + tx] =
            __float2half(t[tx][ty + 8 * j]);
}

// ---------------------------------------------------------------------------
// Fused QKV projection + RoPE, single-pass fp16; double-buffered smem.
// Grid x: 0-15 Q, 16-19 K, 20-23 V. CTA 128x128, BK=32.  (R14 proven)
// ---------------------------------------------------------------------------
#define SAS   40
#define GBUF  (128 * SAS * 2)
#define GSTG2 (2 * GBUF)
#define GEMM_SMEM (2 * GSTG2)

extern __shared__ char dynsm[];

__global__ __launch_bounds__(256) void qkv_gemm(
    const __half* __restrict__ Ah,
    const __half* __restrict__ Wqh, const __half* __restrict__ Wkh,
    const __half* __restrict__ Wvh,
    __half* __restrict__ Qh, __half* __restrict__ Kh, __half* __restrict__ Vh,
    const int* __restrict__ posp)
{
    const int K = C_;
    const int tid = threadIdx.x;
    const int lane = tid & 31, wid = tid >> 5;
    const int wm = wid & 1, wn = wid >> 1;
    const int m0 = blockIdx.y * 128;
    const int nq = blockIdx.x;

    const __half* Bp;
    int mode;                      // 0=Q(rope) 1=K(rope) 2=V
    if (nq < 16)      { Bp = Wqh + (size_t)nq * 128 * K;        mode = 0; }
    else if (nq < 20) { Bp = Wkh + (size_t)(nq - 16) * 128 * K; mode = 1; }
    else              { Bp = Wvh + (size_t)(nq - 20) * 128 * K; mode = 2; }

    const int ldrow = tid >> 1, ldhalf = tid & 1;
    const __half* gAh = Ah + (size_t)(m0 + ldrow) * K + ldhalf * 16;
    const __half* gBh = Bp + (size_t)ldrow * K + ldhalf * 16;
    char* dsm = dynsm + (ldrow * SAS + ldhalf * 16) * 2;

    const int mid = lane >> 3, rin = lane & 7;
    const uint32_t usm = smem_u32(dynsm);
    const uint32_t aoff =
        ((wm * 64 + (mid & 1) * 8 + rin) * SAS + (mid >> 1) * 8) * 2;
    const uint32_t boff =
        ((wn * 16 + (mid >> 1) * 8 + rin) * SAS + (mid & 1) * 8) * 2;
    const uint32_t uAh = usm + aoff;
    const uint32_t uBh = usm + GBUF + boff;

    float acc[4][4][4];
#pragma unroll
    for (int mt = 0; mt < 4; mt++)
#pragma unroll
        for (int nt = 0; nt < 4; nt++)
#pragma unroll
            for (int j = 0; j < 4; j++) acc[mt][nt][j] = 0.0f;

    uint4 rah[2], rbh[2];

#define GLOAD(k0)                                            \
    {                                                        \
        rah[0] = *(const uint4*)(gAh + (k0));                \
        rah[1] = *(const uint4*)(gAh + (k0) + 8);            \
        rbh[0] = *(const uint4*)(gBh + (k0));                \
        rbh[1] = *(const uint4*)(gBh + (k0) + 8);            \
    }
#define SSTORE(stg)                                          \
    {                                                        \
        char* d = dsm + (stg) * GSTG2;                       \
        *(uint4*)(d)             = rah[0];                   \
        *(uint4*)(d + 16)        = rah[1];                   \
        *(uint4*)(d + GBUF)      = rbh[0];                   \
        *(uint4*)(d + GBUF + 16) = rbh[1];                   \
    }

    GLOAD(0);
    SSTORE(0);
    __syncthreads();

    const int nch = K / 32;
    for (int ch = 0; ch < nch; ch++) {
        const bool more = (ch + 1 < nch);
        if (more) GLOAD((ch + 1) * 32);
        const uint32_t so = (ch & 1) * GSTG2;

#pragma unroll
        for (int ks = 0; ks < 2; ks++) {
            uint32_t fah[4][4], fbh[2][4];
#pragma unroll
            for (int mt = 0; mt < 4; mt++)
                ldsm4(fah[mt], uAh + so + mt * (16 * SAS * 2) + ks * 32);
            ldsm4(fbh[0], uBh + so + ks * 32);
            ldsm4(fbh[1], uBh + so + 64 * (SAS * 2) + ks * 32);
#pragma unroll
            for (int mt = 0; mt < 4; mt++)
#pragma unroll
                for (int nt = 0; nt < 4; nt++)
                    mma16816h(acc[mt][nt], fah[mt], &fbh[nt >> 1][(nt & 1) * 2]);
        }
        if (more) {
            SSTORE((ch + 1) & 1);
            __syncthreads();
        }
    }
#undef GLOAD
#undef SSTORE

    const int g = lane >> 2, tg = lane & 3;

    if (mode == 2) {
        const int coff = (nq - 20) * 128;
#pragma unroll
        for (int mt = 0; mt < 4; mt++) {
            const int r0 = m0 + wm * 64 + mt * 16 + g;
#pragma unroll
            for (int nt = 0; nt < 4; nt++) {
                const int c = wn * 16 + (nt & 1) * 8 + ((nt & 2) ? 64 : 0) + tg * 2;
                __half2 h0 = __floats2half2_rn(acc[mt][nt][0], acc[mt][nt][1]);
                __half2 h1 = __floats2half2_rn(acc[mt][nt][2], acc[mt][nt][3]);
                *(uint32_t*)(Vh + (size_t)r0 * KVD + coff + c)       = *(uint32_t*)&h0;
                *(uint32_t*)(Vh + (size_t)(r0 + 8) * KVD + coff + c) = *(uint32_t*)&h1;
            }
        }
        return;
    }

    // Q/K: RoPE on accumulator pairs (nt, nt+2) = cols (c, c+64)
    const int posv = posp[0];
    const float LN1E4_128 = 9.210340371976184f / 128.0f;
#pragma unroll
    for (int mt = 0; mt < 4; mt++) {
        const int mr = m0 + wm * 64 + mt * 16 + g;
#pragma unroll
        for (int nt = 0; nt < 2; nt++) {
            const int c = wn * 16 + nt * 8 + tg * 2;
            const float f1 = __expf(-(float)(2 * (c >> 1)) * LN1E4_128);
            const float f2 = f1 * 0.01f;
#pragma unroll
            for (int rj = 0; rj < 2; rj++) {
                const int row = mr + rj * 8;
                const float pos = (float)(posv + (row & (T_ - 1)));
                const float a1 = pos * f1, a2 = pos * f2;
                const float c1 = cosf(a1), s1 = sinf(a1);
                const float c2 = cosf(a2), s2 = sinf(a2);
                float o1[2], o2[2];
#pragma unroll
                for (int jj = 0; jj < 2; jj++) {
                    const float x1 = acc[mt][nt][rj * 2 + jj];
                    const float x2 = acc[mt][nt + 2][rj * 2 + jj];
                    o1[jj] = x1 * c1 - x2 * s1;
                    o2[jj] = x2 * c2 + x1 * s2;
                }
                __half2 hi1 = __floats2half2_rn(o1[0], o1[1]);
                __half2 hi2 = __floats2half2_rn(o2[0], o2[1]);
                if (mode == 0) {
                    size_t base = (size_t)row * C_ + nq * 128 + c;
                    *(uint32_t*)(Qh + base)      = *(uint32_t*)&hi1;
                    *(uint32_t*)(Qh + base + 64) = *(uint32_t*)&hi2;
                } else {
                    size_t base = (size_t)row * KVD + (nq - 16) * 128 + c;
                    *(uint32_t*)(Kh + base)      = *(uint32_t*)&hi1;
                    *(uint32_t*)(Kh + base + 64) = *(uint32_t*)&hi2;
                }
            }
        }
    }
}

// ---------------------------------------------------------------------------
// fp16 single-pass Wo GEMM; double-buffered smem (R11 proven)
// ---------------------------------------------------------------------------
__global__ __launch_bounds__(256) void gemm_mma1(
    const __half* __restrict__ Ah, const __half* __restrict__ Bh,
    float* __restrict__ C, int N, int K)
{
    const int tid = threadIdx.x;
    const int lane = tid & 31, wid = tid >> 5;
    const int wm = wid & 1, wn = wid >> 1;
    const int m0 = blockIdx.y * 128, n0 = blockIdx.x * 128;

    const int ldrow = tid >> 1, ldhalf = tid & 1;
    const __half* gAh = Ah + (size_t)(m0 + ldrow) * K + ldhalf * 16;
    const __half* gBh = Bh + (size_t)(n0 + ldrow) * K + ldhalf * 16;
    char* dsm = dynsm + (ldrow * SAS + ldhalf * 16) * 2;

    const int mid = lane >> 3, rin = lane & 7;
    const uint32_t usm = smem_u32(dynsm);
    const uint32_t aoff =
        ((wm * 64 + (mid & 1) * 8 + rin) * SAS + (mid >> 1) * 8) * 2;
    const uint32_t boff =
        ((wn * 32 + (mid >> 1) * 8 + rin) * SAS + (mid & 1) * 8) * 2;
    const uint32_t uAh = usm + aoff;
    const uint32_t uBh = usm + GBUF + boff;

    float acc[4][4][4];
#pragma unroll
    for (int mt = 0; mt < 4; mt++)
#pragma unroll
        for (int nt = 0; nt < 4; nt++)
#pragma unroll
            for (int j = 0; j < 4; j++) acc[mt][nt][j] = 0.0f;

    uint4 rah[2], rbh[2];

#define GLOAD(k0)                                            \
    {                                                        \
        rah[0] = *(const uint4*)(gAh + (k0));                \
        rah[1] = *(const uint4*)(gAh + (k0) + 8);            \
        rbh[0] = *(const uint4*)(gBh + (k0));                \
        rbh[1] = *(const uint4*)(gBh + (k0) + 8);            \
    }
#define SSTORE(stg)                                          \
    {                                                        \
        char* d = dsm + (stg) * GSTG2;                       \
        *(uint4*)(d)             = rah[0];                   \
        *(uint4*)(d + 16)        = rah[1];                   \
        *(uint4*)(d + GBUF)      = rbh[0];                   \
        *(uint4*)(d + GBUF + 16) = rbh[1];                   \
    }

    GLOAD(0);
    SSTORE(0);
    __syncthreads();

    const int nch = K / 32;
    for (int ch = 0; ch < nch; ch++) {
        const bool more = (ch + 1 < nch);
        if (more) GLOAD((ch + 1) * 32);
        const uint32_t so = (ch & 1) * GSTG2;

#pragma unroll
        for (int ks = 0; ks < 2; ks++) {
            uint32_t fah[4][4], fbh[2][4];
#pragma unroll
            for (int mt = 0; mt < 4; mt++)
                ldsm4(fah[mt], uAh + so + mt * (16 * SAS * 2) + ks * 32);
#pragma unroll
            for (int np = 0; np < 2; np++)
                ldsm4(fbh[np], uBh + so + np * (16 * SAS * 2) + ks * 32);
#pragma unroll
            for (int mt = 0; mt < 4; mt++)
#pragma unroll
                for (int nt = 0; nt < 4; nt++)
                    mma16816h(acc[mt][nt], fah[mt], &fbh[nt >> 1][(nt & 1) * 2]);
        }
        if (more) {
            SSTORE((ch + 1) & 1);
            __syncthreads();
        }
    }
#undef GLOAD
#undef SSTORE

    const int g = lane >> 2, tg = lane & 3;
#pragma unroll
    for (int mt = 0; mt < 4; mt++) {
        const int mrow = m0 + wm * 64 + mt * 16 + g;
#pragma unroll
        for (int nt = 0; nt < 4; nt++) {
            const int ncol = n0 + wn * 32 + nt * 8 + tg * 2;
            float2 v0 = {acc[mt][nt][0], acc[mt][nt][1]};
            float2 v1 = {acc[mt][nt][2], acc[mt][nt][3]};
            *(float2*)(C + (size_t)mrow * N + ncol)       = v0;
            *(float2*)(C + (size_t)(mrow + 8) * N + ncol) = v1;
        }
    }
}

// ---------------------------------------------------------------------------
// Flash attention (exact R14 config: 128 thr, natural regs, 2 CTAs/SM) with
// long-first CTA ordering: qb = gridDim.x-1-blockIdx.x (LPT scheduling).
// cp.async double-buffered K/V, single-pass fp16 QK and PV.
// ---------------------------------------------------------------------------
#define SKP 136
#define FSTG (2 * 64 * SKP * 2)      // one stage: Kh + Vh (34816 B)
#define FL_SMEM (2 * FSTG)

__global__ __launch_bounds__(128) void flash_mma(
    const __half* __restrict__ Qh,
    const __half* __restrict__ Khg, const __half* __restrict__ Vhg,
    __half* __restrict__ Yh)
{
    const int tid = threadIdx.x, lane = tid & 31, w = tid >> 5;
    const int qb = gridDim.x - 1 - blockIdx.x;    // longest work first
    const int h = blockIdx.y, b = blockIdx.z;
    const int kvh = h >> 2;
    const int g = lane >> 2, tg = lane & 3;
    const int mid = lane >> 3, rin = lane & 7;
    const int qrow0 = qb * 64 + w * 16;

    uint32_t qh[8][4];
    {
        const __half* Qhb = Qh + ((size_t)b * T_ + qrow0) * C_ + h * HD;
#pragma unroll
        for (int kc = 0; kc < 8; kc++) {
#pragma unroll
            for (int fr = 0; fr < 4; fr++) {
                int r = g + (fr & 1) * 8;
                int c = kc * 16 + tg * 2 + (fr >> 1) * 8;
                qh[kc][fr] = *(const uint32_t*)(Qhb + (size_t)r * C_ + c);
            }
        }
    }

    float o[16][4];
#pragma unroll
    for (int nt = 0; nt < 16; nt++)
#pragma unroll
        for (int j = 0; j < 4; j++) o[nt][j] = 0.0f;
    float m0 = -INFINITY, m1 = -INFINITY, l0 = 0.0f, l1 = 0.0f;

    const float cscale = 0.08838834764831845f;
    const int rg0 = qrow0 + g, rg1 = rg0 + 8;
    const int ktmax = qb + 1;

    const __half* Kh0 = Khg + (size_t)b * T_ * KVD + kvh * HD;
    const __half* Vh0 = Vhg + (size_t)b * T_ * KVD + kvh * HD;

    const uint32_t usm = smem_u32(dynsm);
    const uint32_t uK = usm, uV = usm + 64 * SKP * 2;
    const uint32_t kfrag = (((mid >> 1) * 8 + rin) * SKP + (mid & 1) * 8) * 2;
    const uint32_t vfrag = (((mid & 1) * 8 + rin) * SKP + (mid >> 1) * 8) * 2;

    const int lr = tid >> 4, lc8 = (tid & 15) << 3;

#define FLOAD(stg, kt)                                                        \
    {                                                                         \
        const __half* Kt = Kh0 + (size_t)(kt) * 64 * KVD;                     \
        const __half* Vt = Vh0 + (size_t)(kt) * 64 * KVD;                     \
        uint32_t base = usm + (stg) * FSTG;                                   \
        _Pragma("unroll")                                                     \
        for (int it = 0; it < 8; it++) {                                      \
            int r = lr + it * 8;                                              \
            uint32_t so = base + (r * SKP + lc8) * 2;                         \
            cpa16(so,                 Kt + (size_t)r * KVD + lc8);            \
            cpa16(so + 64 * SKP * 2,  Vt + (size_t)r * KVD + lc8);            \
        }                                                                     \
        cp_commit();                                                          \
    }

    FLOAD(0, 0);

    for (int kt = 0; kt < ktmax; kt++) {
        const bool more = (kt + 1 < ktmax);
        if (more) FLOAD((kt + 1) & 1, kt + 1);
        if (more) cp_wait1(); else cp_wait0();
        __syncthreads();

        const uint32_t so = (kt & 1) * FSTG;
        const uint32_t uKh = uK + so, uVh = uV + so;

        {
            const bool needmask = (kt * 64 + 63 > qrow0);

            float s[8][4];
#pragma unroll
            for (int nt = 0; nt < 8; nt++)
#pragma unroll
                for (int j = 0; j < 4; j++) s[nt][j] = 0.0f;

#pragma unroll
            for (int kc = 0; kc < 8; kc++) {
                uint32_t bt[4][4];
#pragma unroll
                for (int nt2 = 0; nt2 < 4; nt2++)
                    ldsm4(bt[nt2], uKh + kfrag + (nt2 * 16 * SKP + kc * 16) * 2);
#pragma unroll
                for (int nt = 0; nt < 8; nt++)
                    mma16816h(s[nt], qh[kc], &bt[nt >> 1][(nt & 1) * 2]);
            }

#pragma unroll
            for (int nt = 0; nt < 8; nt++) {
#pragma unroll
                for (int j = 0; j < 4; j++) s[nt][j] *= cscale;
                if (needmask) {
                    int c0 = kt * 64 + nt * 8 + tg * 2;
                    if (c0 > rg0)     s[nt][0] = -1e30f;
                    if (c0 + 1 > rg0) s[nt][1] = -1e30f;
                    if (c0 > rg1)     s[nt][2] = -1e30f;
                    if (c0 + 1 > rg1) s[nt][3] = -1e30f;
                }
            }

            float mn0 = m0, mn1 = m1;
#pragma unroll
            for (int nt = 0; nt < 8; nt++) {
                mn0 = fmaxf(mn0, fmaxf(s[nt][0], s[nt][1]));
                mn1 = fmaxf(mn1, fmaxf(s[nt][2], s[nt][3]));
            }
            mn0 = fmaxf(mn0, __shfl_xor_sync(0xffffffffu, mn0, 1));
            mn0 = fmaxf(mn0, __shfl_xor_sync(0xffffffffu, mn0, 2));
            mn1 = fmaxf(mn1, __shfl_xor_sync(0xffffffffu, mn1, 1));
            mn1 = fmaxf(mn1, __shfl_xor_sync(0xffffffffu, mn1, 2));
            float fac0 = __expf(m0 - mn0), fac1 = __expf(m1 - mn1);
            m0 = mn0; m1 = mn1;

            uint32_t pa[4][4];
            float ps0 = 0.0f, ps1 = 0.0f;
#pragma unroll
            for (int kk = 0; kk < 4; kk++) {
                int nt = 2 * kk;
                float p00 = __expf(s[nt][0] - m0),     p01 = __expf(s[nt][1] - m0);
                float p02 = __expf(s[nt][2] - m1),     p03 = __expf(s[nt][3] - m1);
                float p10 = __expf(s[nt + 1][0] - m0), p11 = __expf(s[nt + 1][1] - m0);
                float p12 = __expf(s[nt + 1][2] - m1), p13 = __expf(s[nt + 1][3] - m1);
                ps0 += p00 + p01 + p10 + p11;
                ps1 += p02 + p03 + p12 + p13;
                __half2 a0 = __floats2half2_rn(p00, p01);
                __half2 a1 = __floats2half2_rn(p02, p03);
                __half2 a2 = __floats2half2_rn(p10, p11);
                __half2 a3 = __floats2half2_rn(p12, p13);
                pa[kk][0] = *(uint32_t*)&a0;
                pa[kk][1] = *(uint32_t*)&a1;
                pa[kk][2] = *(uint32_t*)&a2;
                pa[kk][3] = *(uint32_t*)&a3;
            }
            l0 = l0 * fac0 + ps0;
            l1 = l1 * fac1 + ps1;

#pragma unroll
            for (int nt = 0; nt < 16; nt++) {
                o[nt][0] *= fac0; o[nt][1] *= fac0;
                o[nt][2] *= fac1; o[nt][3] *= fac1;
            }

#pragma unroll
            for (int kk = 0; kk < 4; kk++) {
                uint32_t vb[8][4];
#pragma unroll
                for (int np = 0; np < 8; np++)
                    ldsm4t(vb[np], uVh + vfrag + (kk * 16 * SKP + np * 16) * 2);
#pragma unroll
                for (int nt = 0; nt < 16; nt++)
                    mma16816h(o[nt], pa[kk], &vb[nt >> 1][(nt & 1) * 2]);
            }
        }
        __syncthreads();
    }
#undef FLOAD

    l0 += __shfl_xor_sync(0xffffffffu, l0, 1);
    l0 += __shfl_xor_sync(0xffffffffu, l0, 2);
    l1 += __shfl_xor_sync(0xffffffffu, l1, 1);
    l1 += __shfl_xor_sync(0xffffffffu, l1, 2);
    float inv0 = 1.0f / l0, inv1 = 1.0f / l1;

    size_t row0 = (size_t)b * T_ + rg0;
    size_t row1 = (size_t)b * T_ + rg1;
#pragma unroll
    for (int nt = 0; nt < 16; nt++) {
        int col = h * HD + nt * 8 + tg * 2;
        __half2 h0 = __floats2half2_rn(o[nt][0] * inv0, o[nt][1] * inv0);
        __half2 h1 = __floats2half2_rn(o[nt][2] * inv1, o[nt][3] * inv1);
        *(uint32_t*)(Yh + row0 * C_ + col) = *(uint32_t*)&h0;
        *(uint32_t*)(Yh + row1 * C_ + col) = *(uint32_t*)&h1;
    }
}

// ---------------------------------------------------------------------------
extern "C" void kernel_launch(void* const* d_in, const int* in_sizes, int n_in,
                              void* d_out, int out_size)
{
    const float* x  = (const float*)d_in[0];
    const float* Wq = (const float*)d_in[1];
    const float* Wk = (const float*)d_in[2];
    const float* Wv = (const float*)d_in[3];
    const float* Wo = (const float*)d_in[4];
    const int*  pos = (const int*)d_in[5];
    float* out = (float*)d_out;

    __half *qh, *kh, *vh;
    cudaGetSymbolAddress((void**)&qh, s_qh);
    cudaGetSymbolAddress((void**)&kh, s_kh);
    cudaGetSymbolAddress((void**)&vh, s_vh);
    __half *xh, *yh, *wqh, *wkh, *wvh, *woh;
    cudaGetSymbolAddress((void**)&xh, s_xh);
    cudaGetSymbolAddress((void**)&yh, s_yh);
    cudaGetSymbolAddress((void**)&wqh, s_wqh);
    cudaGetSymbolAddress((void**)&wkh, s_wkh);
    cudaGetSymbolAddress((void**)&wvh, s_wvh);
    cudaGetSymbolAddress((void**)&woh, s_woh);

    cudaFuncSetAttribute(qkv_gemm, cudaFuncAttributeMaxDynamicSharedMemorySize,
                         GEMM_SMEM);
    cudaFuncSetAttribute(gemm_mma1, cudaFuncAttributeMaxDynamicSharedMemorySize,
                         GEMM_SMEM);
    cudaFuncSetAttribute(flash_mma, cudaFuncAttributeMaxDynamicSharedMemorySize,
                         FL_SMEM);

    {
        int n4 = M_ * C_ / 4;
        convert_kernel<<<(n4 + 255) / 256, 256>>>(x, xh, n4);
    }
    transpose_all_kernel<<<dim3(C_ / 32, C_ / 32, 4), dim3(32, 8)>>>(
        Wq, Wk, Wv, Wo, wqh, wkh, wvh, woh);

    qkv_gemm<<<dim3(24, M_ / 128), 256, GEMM_SMEM>>>(xh, wqh, wkh, wvh,
                                                     qh, kh, vh, pos);

    flash_mma<<<dim3(T_ / 64, NH, B_), 128, FL_SMEM>>>(qh, kh, vh, yh);

    gemm_mma1<<<dim3(C_ / 128, M_ / 128), 256, GEMM_SMEM>>>(yh, woh, out, C_, C_);
}